// round 1
// baseline (speedup 1.0000x reference)
#include <cuda_runtime.h>
#include <cuda_bf16.h>

#define N_ATOM 30000
#define N_PAIR 1000000
#define N_TRI  4000000
#define N_SF   16
#define RC2    36.0f
#define PI_OVER_RC 0.52359877559f  // pi / 6

// Scratch: per-pair segment-max accumulator (device global, no allocation).
__device__ int g_pair_max[N_PAIR];

__constant__ float c_eta[N_SF] = {
    0.01f, 0.014f, 0.02f, 0.028f, 0.04f, 0.056f, 0.08f, 0.11f,
    0.16f, 0.22f, 0.32f, 0.45f, 0.63f, 0.72f, 0.9f, 1.0f
};

// ---------------------------------------------------------------------------
// Kernel 1: zero fp region of d_out, init pair_max to -1
// (empty segments in jax segment_max -> max(.., -1) == -1)
// ---------------------------------------------------------------------------
__global__ void init_kernel(float* __restrict__ fp)
{
    int i = blockIdx.x * blockDim.x + threadIdx.x;
    if (i < N_ATOM * N_SF) fp[i] = 0.0f;
    if (i < N_PAIR)        g_pair_max[i] = -1;
}

// ---------------------------------------------------------------------------
// Kernel 2: main triple loop.
//   sf_k = 2^(1-z_k) * max(1 + l_k*cos, 0)^z_k
//          * fc_ij*fc_ik*fc_jk * exp(-eta_k * (d_ij^2 + d_ik^2 + d_jk^2))
//   lambda alternates (-1,+1); zeta = (1,1,2,2,4,4,8,8) x2.
// ---------------------------------------------------------------------------
__global__ void __launch_bounds__(256) tri_kernel(
    const int*  __restrict__ ind2,   // [N_PAIR, 2]
    const int2* __restrict__ ind3,   // [N_TRI, 2]
    const float* __restrict__ dist,  // [N_PAIR]
    const float* __restrict__ diff,  // [N_PAIR, 3]
    const float* __restrict__ fc,    // [N_PAIR]
    float* __restrict__ fp)          // [N_ATOM, N_SF]
{
    int t = blockIdx.x * blockDim.x + threadIdx.x;
    if (t >= N_TRI) return;

    int2 pr = __ldg(&ind3[t]);
    int ij = pr.x;
    int ik = pr.y;

    float ax = __ldg(diff + 3 * ij);
    float ay = __ldg(diff + 3 * ij + 1);
    float az = __ldg(diff + 3 * ij + 2);
    float bx = __ldg(diff + 3 * ik);
    float by = __ldg(diff + 3 * ik + 1);
    float bz = __ldg(diff + 3 * ik + 2);

    float jx = bx - ax, jy = by - ay, jz = bz - az;
    float djk2 = jx * jx + jy * jy + jz * jz;

    if (djk2 >= RC2) return;  // sf masked to zero AND segment-max val == -1 (init)

    float dij  = __ldg(dist + ij);
    float dik  = __ldg(dist + ik);
    float fcij = __ldg(fc + ij);
    float fcik = __ldg(fc + ik);
    int i_rind = __ldg(ind2 + 2 * ij);

    float djk  = sqrtf(djk2);
    float fcjk = 0.5f * (__cosf(PI_OVER_RC * djk) + 1.0f);

    float dot  = ax * bx + ay * by + az * bz;
    float cosv = __fdividef(dot, dij * dik);

    float a = fmaxf(1.0f - cosv, 0.0f);   // lambda = -1 channels
    float b = fmaxf(1.0f + cosv, 0.0f);   // lambda = +1 channels

    float P  = fcij * fcik * fcjk;        // product of cutoffs
    float Ph = 0.5f * P;                  // 2^(1-2)
    float Pq = 0.125f * P;                // 2^(1-4)
    float Pe = 0.0078125f * P;            // 2^(1-8)

    float a2 = a * a,  b2 = b * b;
    float a4 = a2 * a2, b4 = b2 * b2;
    float a8 = a4 * a4, b8 = b4 * b4;

    float q[8];
    q[0] = a  * P;  q[1] = b  * P;
    q[2] = a2 * Ph; q[3] = b2 * Ph;
    q[4] = a4 * Pq; q[5] = b4 * Pq;
    q[6] = a8 * Pe; q[7] = b8 * Pe;

    float s = dij * dij + dik * dik + djk2;  // shared exponent argument

    float* dst = fp + i_rind * N_SF;
#pragma unroll
    for (int k = 0; k < N_SF; k++) {
        float sf = q[k & 7] * __expf(-c_eta[k] * s);
        atomicAdd(dst + k, sf);
    }

    // segment-max contribution (only masked triples contribute > -1)
    atomicMax(&g_pair_max[ij], i_rind);
    atomicMax(&g_pair_max[ik], i_rind);
}

// ---------------------------------------------------------------------------
// Kernel 3: emit jacob_ind = [arange(N_PAIR), pair_max] as float values
// (all values integers <= 1e6 or -1: exactly representable in fp32)
// ---------------------------------------------------------------------------
__global__ void jac_kernel(float* __restrict__ out_j)
{
    int p = blockIdx.x * blockDim.x + threadIdx.x;
    if (p < N_PAIR) {
        out_j[2 * p]     = (float)p;
        out_j[2 * p + 1] = (float)g_pair_max[p];
    }
}

// ---------------------------------------------------------------------------
// Launch. Input order (metadata): ind_2, ind_3, dist, diff, elems, fc
// Output: fp [30000,16] fp32, then jacob_ind [1M,2]
// ---------------------------------------------------------------------------
extern "C" void kernel_launch(void* const* d_in, const int* in_sizes, int n_in,
                              void* d_out, int out_size)
{
    const int*   ind2  = (const int*)d_in[0];
    const int2*  ind3  = (const int2*)d_in[1];
    const float* dist  = (const float*)d_in[2];
    const float* diff  = (const float*)d_in[3];
    // d_in[4] = elems (unused by reference output)
    const float* fc    = (const float*)d_in[5];

    float* fp    = (float*)d_out;
    float* out_j = (float*)d_out + N_ATOM * N_SF;

    const int T = 256;
    init_kernel<<<(N_PAIR + T - 1) / T, T>>>(fp);
    tri_kernel<<<(N_TRI + T - 1) / T, T>>>(ind2, ind3, dist, diff, fc, fp);
    jac_kernel<<<(N_PAIR + T - 1) / T, T>>>(out_j);
}

// round 2
// speedup vs baseline: 2.1626x; 2.1626x over previous
#include <cuda_runtime.h>
#include <cuda_bf16.h>

#define N_ATOM 30000
#define N_PAIR 1000000
#define N_TRI  4000000
#define N_SF   16
#define RC2    36.0f
#define U_SCALE 0.27415567780803773f  // pi^2 / 36

// Scratch: per-pair segment-max accumulator (device global, no allocation).
__device__ int g_pair_max[N_PAIR];

// ---------------------------------------------------------------------------
// Kernel 1: zero fp region of d_out, init pair_max to -1
// ---------------------------------------------------------------------------
__global__ void init_kernel(float* __restrict__ fp)
{
    int i = blockIdx.x * blockDim.x + threadIdx.x;
    if (i < N_ATOM * N_SF) fp[i] = 0.0f;
    if (i < N_PAIR)        g_pair_max[i] = -1;
}

// Vector reduction: 4 floats, one REDG (sm_90+)
__device__ __forceinline__ void red_add_v4(float* addr, float a, float b, float c, float d)
{
    asm volatile("red.global.add.v4.f32 [%0], {%1, %2, %3, %4};"
                 :: "l"(addr), "f"(a), "f"(b), "f"(c), "f"(d) : "memory");
}

// 0.5*(cos(pi*sqrt(x)/6)+1) as poly in u = (pi^2/36)*x.
// cos(sqrt(u')) Taylor: sum (-1)^k u^k/(2k)!, k=0..9, |err| < 4e-9 on [0, pi^2].
__device__ __forceinline__ float fc_from_d2(float d2)
{
    float u = d2 * U_SCALE;
    float p = -2.7557319e-07f;             // -1/3628800  (k=5)
    p = fmaf(p, u,  2.4801587e-05f);       //  1/40320
    p = fmaf(p, u, -1.3888889e-03f);       // -1/720
    p = fmaf(p, u,  4.1666667e-02f);       //  1/24
    p = fmaf(p, u, -0.5f);
    p = fmaf(p, u,  1.0f);
    // extend with high-order correction terms (k=6..9) for full accuracy:
    float u2 = u * u;
    float u3 = u2 * u;
    float hi = 2.0876757e-09f;             //  1/479001600 (k=6)
    hi = fmaf(hi, u, 0.0f);                // placeholder keeps compiler from reordering badly
    float corr = u3 * u3 * (2.0876757e-09f
               + u * (-1.1470746e-11f
               + u * ( 4.7794773e-14f
               + u * (-1.5619207e-16f))));
    float cosv = p + corr;
    return 0.5f * (cosv + 1.0f);
}

// ---------------------------------------------------------------------------
// Kernel 2: main triple loop.
// ---------------------------------------------------------------------------
__global__ void __launch_bounds__(256) tri_kernel(
    const int*   __restrict__ ind2,   // [N_PAIR, 2]
    const int2*  __restrict__ ind3,   // [N_TRI, 2]
    const float* __restrict__ diff,   // [N_PAIR, 3]
    const float* __restrict__ fc,     // [N_PAIR]
    float* __restrict__ fp)           // [N_ATOM, N_SF]
{
    int t = blockIdx.x * blockDim.x + threadIdx.x;
    if (t >= N_TRI) return;

    int2 pr = __ldg(&ind3[t]);
    int ij = pr.x;
    int ik = pr.y;

    float ax = __ldg(diff + 3 * ij);
    float ay = __ldg(diff + 3 * ij + 1);
    float az = __ldg(diff + 3 * ij + 2);
    float bx = __ldg(diff + 3 * ik);
    float by = __ldg(diff + 3 * ik + 1);
    float bz = __ldg(diff + 3 * ik + 2);

    float jx = bx - ax, jy = by - ay, jz = bz - az;
    float djk2 = jx * jx + jy * jy + jz * jz;

    if (djk2 >= RC2) return;   // sf masked to 0; seg-max contribution == -1 == init

    float dij2 = ax * ax + ay * ay + az * az;
    float dik2 = bx * bx + by * by + bz * bz;

    float fcij = __ldg(fc + ij);
    float fcik = __ldg(fc + ik);
    int i_rind = __ldg(ind2 + 2 * ij);

    float fcjk = fc_from_d2(djk2);

    float dot  = ax * bx + ay * by + az * bz;
    float cosv = dot * rsqrtf(dij2 * dik2);

    float a = fmaxf(1.0f - cosv, 0.0f);   // lambda = -1 channels
    float b = fmaxf(1.0f + cosv, 0.0f);   // lambda = +1 channels

    float P  = fcij * fcik * fcjk;
    float Ph = 0.5f * P;                  // 2^(1-2)
    float Pq = 0.125f * P;                // 2^(1-4)
    float Pe = 0.0078125f * P;            // 2^(1-8)

    float a2 = a * a,  b2 = b * b;
    float a4 = a2 * a2, b4 = b2 * b2;
    float a8 = a4 * a4, b8 = b4 * b4;

    float q0 = a  * P;  float q1 = b  * P;
    float q2 = a2 * Ph; float q3 = b2 * Ph;
    float q4 = a4 * Pq; float q5 = b4 * Pq;
    float q6 = a8 * Pe; float q7 = b8 * Pe;

    float s = dij2 + dik2 + djk2;   // shared exponent argument

    // Two transcendentals, everything else integer powers.
    float e1   = __expf(-0.01f  * s);
    float e14  = __expf(-0.014f * s);

    float e2   = e1  * e1;
    float e4   = e2  * e2;
    float e8   = e4  * e4;
    float e16  = e8  * e8;
    float e32  = e16 * e16;
    float e64  = e32 * e32;

    float e3   = e2  * e1;
    float e11  = e8  * e3;
    float e22  = e11 * e11;
    float e44  = e22 * e22;
    float e45  = e44 * e1;
    float e63  = e45 * (e16 * e2);
    float e72  = e64 * e8;
    float e90  = e45 * e45;
    float e100 = e64 * (e32 * e4);

    float e14_2 = e14  * e14;
    float e14_4 = e14_2 * e14_2;

    float* dst = fp + i_rind * N_SF;
    // eta order: .01 .014 .02 .028 | .04 .056 .08 .11 | .16 .22 .32 .45 | .63 .72 .9 1.0
    red_add_v4(dst +  0, q0 * e1,   q1 * e14,   q2 * e2,   q3 * e14_2);
    red_add_v4(dst +  4, q4 * e4,   q5 * e14_4, q6 * e8,   q7 * e11);
    red_add_v4(dst +  8, q0 * e16,  q1 * e22,   q2 * e32,  q3 * e45);
    red_add_v4(dst + 12, q4 * e63,  q5 * e72,   q6 * e90,  q7 * e100);

    atomicMax(&g_pair_max[ij], i_rind);
    atomicMax(&g_pair_max[ik], i_rind);
}

// ---------------------------------------------------------------------------
// Kernel 3: emit jacob_ind = [arange(N_PAIR), pair_max] as float values
// ---------------------------------------------------------------------------
__global__ void jac_kernel(float* __restrict__ out_j)
{
    int p = blockIdx.x * blockDim.x + threadIdx.x;
    if (p < N_PAIR) {
        out_j[2 * p]     = (float)p;
        out_j[2 * p + 1] = (float)g_pair_max[p];
    }
}

// ---------------------------------------------------------------------------
// Launch. Inputs: ind_2, ind_3, dist(unused), diff, elems(unused), fc
// ---------------------------------------------------------------------------
extern "C" void kernel_launch(void* const* d_in, const int* in_sizes, int n_in,
                              void* d_out, int out_size)
{
    const int*   ind2  = (const int*)d_in[0];
    const int2*  ind3  = (const int2*)d_in[1];
    const float* diff  = (const float*)d_in[3];
    const float* fc    = (const float*)d_in[5];

    float* fp    = (float*)d_out;
    float* out_j = (float*)d_out + N_ATOM * N_SF;

    const int T = 256;
    init_kernel<<<(N_PAIR + T - 1) / T, T>>>(fp);
    tri_kernel<<<(N_TRI + T - 1) / T, T>>>(ind2, ind3, diff, fc, fp);
    jac_kernel<<<(N_PAIR + T - 1) / T, T>>>(out_j);
}

// round 3
// speedup vs baseline: 2.5871x; 1.1963x over previous
#include <cuda_runtime.h>
#include <cuda_bf16.h>

#define N_ATOM 30000
#define N_PAIR 1000000
#define N_TRI  4000000
#define N_SF   16
#define RC2    36.0f
#define U_SCALE 0.27415567780803773f  // pi^2 / 36

// 32B-aligned per-pair packet: one L2 sector fetch serves a whole pair role.
struct __align__(32) PairDat {
    float dx, dy, dz, fc;
    int   rind;           // ind2[p*2] (atom index i of pair p)
    int   pad0, pad1, pad2;
};

__device__ PairDat g_pair[N_PAIR];       // 32MB scratch (static, no alloc)
__device__ int     g_pair_max[N_PAIR];   // segment-max accumulator

// ---------------------------------------------------------------------------
// Kernel 1 (fused): pack pair data + init pair_max + zero fp
// ---------------------------------------------------------------------------
__global__ void __launch_bounds__(256) pack_init_kernel(
    const int*   __restrict__ ind2,
    const float* __restrict__ diff,
    const float* __restrict__ fc,
    float* __restrict__ fp)
{
    int p = blockIdx.x * blockDim.x + threadIdx.x;
    if (p < N_PAIR) {
        PairDat pd;
        pd.dx   = __ldg(diff + 3 * p);
        pd.dy   = __ldg(diff + 3 * p + 1);
        pd.dz   = __ldg(diff + 3 * p + 2);
        pd.fc   = __ldg(fc + p);
        pd.rind = __ldg(ind2 + 2 * p);
        pd.pad0 = pd.pad1 = pd.pad2 = 0;
        // two 16B stores, coalesced
        reinterpret_cast<float4*>(&g_pair[p])[0] = make_float4(pd.dx, pd.dy, pd.dz, pd.fc);
        reinterpret_cast<int4*>(&g_pair[p])[1]   = make_int4(pd.rind, 0, 0, 0);
        g_pair_max[p] = -1;
    }
    if (p < N_ATOM * N_SF) fp[p] = 0.0f;
}

// Vector reduction: 4 floats, one REDG (sm_90+)
__device__ __forceinline__ void red_add_v4(float* addr, float a, float b, float c, float d)
{
    asm volatile("red.global.add.v4.f32 [%0], {%1, %2, %3, %4};"
                 :: "l"(addr), "f"(a), "f"(b), "f"(c), "f"(d) : "memory");
}

// 0.5*(cos(pi*sqrt(x)/6)+1) as poly in u = (pi^2/36)*x; |err| < ~4e-9 on domain.
__device__ __forceinline__ float fc_from_d2(float d2)
{
    float u = d2 * U_SCALE;
    float p = -2.7557319e-07f;
    p = fmaf(p, u,  2.4801587e-05f);
    p = fmaf(p, u, -1.3888889e-03f);
    p = fmaf(p, u,  4.1666667e-02f);
    p = fmaf(p, u, -0.5f);
    p = fmaf(p, u,  1.0f);
    float u2 = u * u;
    float u3 = u2 * u;
    float corr = u3 * u3 * (2.0876757e-09f
               + u * (-1.1470746e-11f
               + u * ( 4.7794773e-14f
               + u * (-1.5619207e-16f))));
    float cosv = p + corr;
    return 0.5f * (cosv + 1.0f);
}

// ---------------------------------------------------------------------------
// Kernel 2: main triple loop. Gathers = 2 sectors/triple from packed structs.
// ---------------------------------------------------------------------------
__global__ void __launch_bounds__(256) tri_kernel(
    const int2* __restrict__ ind3,   // [N_TRI, 2]
    float* __restrict__ fp)          // [N_ATOM, N_SF]
{
    int t = blockIdx.x * blockDim.x + threadIdx.x;
    if (t >= N_TRI) return;

    int2 pr = __ldg(&ind3[t]);
    int ij = pr.x;
    int ik = pr.y;

    // One 16B vector load per pair role (+ rind from the same sector for ij)
    const float4* pij4 = reinterpret_cast<const float4*>(&g_pair[ij]);
    const float4* pik4 = reinterpret_cast<const float4*>(&g_pair[ik]);
    float4 A = __ldg(pij4);      // dx,dy,dz,fc of ij
    float4 B = __ldg(pik4);      // dx,dy,dz,fc of ik
    int i_rind = __ldg(&g_pair[ij].rind);

    float jx = B.x - A.x, jy = B.y - A.y, jz = B.z - A.z;
    float djk2 = jx * jx + jy * jy + jz * jz;

    if (djk2 >= RC2) return;   // sf masked to 0; seg-max contribution == -1 == init

    float dij2 = A.x * A.x + A.y * A.y + A.z * A.z;
    float dik2 = B.x * B.x + B.y * B.y + B.z * B.z;

    float fcjk = fc_from_d2(djk2);

    float dot  = A.x * B.x + A.y * B.y + A.z * B.z;
    float cosv = dot * rsqrtf(dij2 * dik2);

    float a = fmaxf(1.0f - cosv, 0.0f);   // lambda = -1 channels
    float b = fmaxf(1.0f + cosv, 0.0f);   // lambda = +1 channels

    float P  = A.w * B.w * fcjk;
    float Ph = 0.5f * P;
    float Pq = 0.125f * P;
    float Pe = 0.0078125f * P;

    float a2 = a * a,  b2 = b * b;
    float a4 = a2 * a2, b4 = b2 * b2;
    float a8 = a4 * a4, b8 = b4 * b4;

    float q0 = a  * P;  float q1 = b  * P;
    float q2 = a2 * Ph; float q3 = b2 * Ph;
    float q4 = a4 * Pq; float q5 = b4 * Pq;
    float q6 = a8 * Pe; float q7 = b8 * Pe;

    float s = dij2 + dik2 + djk2;   // shared exponent argument

    float e1   = __expf(-0.01f  * s);
    float e14  = __expf(-0.014f * s);

    float e2   = e1  * e1;
    float e4   = e2  * e2;
    float e8   = e4  * e4;
    float e16  = e8  * e8;
    float e32  = e16 * e16;
    float e64  = e32 * e32;

    float e3   = e2  * e1;
    float e11  = e8  * e3;
    float e22  = e11 * e11;
    float e44  = e22 * e22;
    float e45  = e44 * e1;
    float e63  = e45 * (e16 * e2);
    float e72  = e64 * e8;
    float e90  = e45 * e45;
    float e100 = e64 * (e32 * e4);

    float e14_2 = e14  * e14;
    float e14_4 = e14_2 * e14_2;

    float* dst = fp + i_rind * N_SF;
    red_add_v4(dst +  0, q0 * e1,   q1 * e14,   q2 * e2,   q3 * e14_2);
    red_add_v4(dst +  4, q4 * e4,   q5 * e14_4, q6 * e8,   q7 * e11);
    red_add_v4(dst +  8, q0 * e16,  q1 * e22,   q2 * e32,  q3 * e45);
    red_add_v4(dst + 12, q4 * e63,  q5 * e72,   q6 * e90,  q7 * e100);

    atomicMax(&g_pair_max[ij], i_rind);
    atomicMax(&g_pair_max[ik], i_rind);
}

// ---------------------------------------------------------------------------
// Kernel 3: jacob_ind = [arange(N_PAIR), pair_max] as float values
// ---------------------------------------------------------------------------
__global__ void jac_kernel(float* __restrict__ out_j)
{
    int p = blockIdx.x * blockDim.x + threadIdx.x;
    if (p < N_PAIR) {
        out_j[2 * p]     = (float)p;
        out_j[2 * p + 1] = (float)g_pair_max[p];
    }
}

// ---------------------------------------------------------------------------
// Launch. Inputs: ind_2, ind_3, dist(unused), diff, elems(unused), fc
// ---------------------------------------------------------------------------
extern "C" void kernel_launch(void* const* d_in, const int* in_sizes, int n_in,
                              void* d_out, int out_size)
{
    const int*   ind2  = (const int*)d_in[0];
    const int2*  ind3  = (const int2*)d_in[1];
    const float* diff  = (const float*)d_in[3];
    const float* fc    = (const float*)d_in[5];

    float* fp    = (float*)d_out;
    float* out_j = (float*)d_out + N_ATOM * N_SF;

    const int T = 256;
    pack_init_kernel<<<(N_PAIR + T - 1) / T, T>>>(ind2, diff, fc, fp);
    tri_kernel<<<(N_TRI + T - 1) / T, T>>>(ind3, fp);
    jac_kernel<<<(N_PAIR + T - 1) / T, T>>>(out_j);
}